// round 10
// baseline (speedup 1.0000x reference)
#include <cuda_runtime.h>

// CrossLayer DCN, closed form, warp-per-2-rows, x re-loaded via L1:
//   t_l = <x, W_l>;  s1 = 1+t1; s2 = s1 + (s1*t2 + c2); s3 = s2 + (s2*t3 + c3)
//   out = x * s3 + (b1+b2+b3);  c2 = <b1,W2>, c3 = <b1+b2,W3>
//
// Block = 256 threads = 8 warps; W/bsum staged in smem (16KB).
// Each warp handles TWO rows (W/bs LDS shared across both). x is NOT held
// across the reduction: first pass loads with default caching (L1-resident),
// output pass re-loads (L1 hits). Registers drop ~106 -> <=64, giving
// 4 blocks/SM (32 warps) instead of 2 (16 warps).

#define D 1024
#define DV (D / 4)
#define THREADS 256
#define WARPS 8
#define ROWS_PER_BLOCK (WARPS * 2)   // 16

__global__ __launch_bounds__(THREADS, 4)
void cross_layer_kernel(const float4* __restrict__ x4,
                        const float4* __restrict__ W4,
                        const float4* __restrict__ b4,
                        float4* __restrict__ out4)
{
    const int tid  = threadIdx.x;
    const int lane = tid & 31;
    const int wid  = tid >> 5;

    __shared__ float4 sW1[DV], sW2[DV], sW3[DV], sBs[DV];
    __shared__ float2 sRed[WARPS];

    // ---- staging: W, bsum -> smem; c2,c3 block-reduced ----
    {
        float4 w1 = __ldg(&W4[tid]);
        float4 w2 = __ldg(&W4[DV + tid]);
        float4 w3 = __ldg(&W4[2 * DV + tid]);
        float4 b1 = __ldg(&b4[tid]);
        float4 b2 = __ldg(&b4[DV + tid]);
        float4 b3 = __ldg(&b4[2 * DV + tid]);

        sW1[tid] = w1; sW2[tid] = w2; sW3[tid] = w3;
        float4 bs;
        bs.x = b1.x + b2.x + b3.x;
        bs.y = b1.y + b2.y + b3.y;
        bs.z = b1.z + b2.z + b3.z;
        bs.w = b1.w + b2.w + b3.w;
        sBs[tid] = bs;

        float p2 = b1.x * w2.x + b1.y * w2.y + b1.z * w2.z + b1.w * w2.w;
        float b12x = b1.x + b2.x, b12y = b1.y + b2.y;
        float b12z = b1.z + b2.z, b12w = b1.w + b2.w;
        float p3 = b12x * w3.x + b12y * w3.y + b12z * w3.z + b12w * w3.w;

        #pragma unroll
        for (int o = 16; o > 0; o >>= 1) {
            p2 += __shfl_xor_sync(0xFFFFFFFFu, p2, o);
            p3 += __shfl_xor_sync(0xFFFFFFFFu, p3, o);
        }
        if (lane == 0) sRed[wid] = make_float2(p2, p3);
    }
    __syncthreads();

    float c2 = 0.f, c3 = 0.f;
    #pragma unroll
    for (int i = 0; i < WARPS; i++) { c2 += sRed[i].x; c3 += sRed[i].y; }

    // ---- row phase: two rows per warp, no barriers ----
    const int rowA  = blockIdx.x * ROWS_PER_BLOCK + wid * 2;
    const int baseA = rowA * DV + lane;
    const int baseB = baseA + DV;

    // dot pass: x loaded with default caching (stays in L1 for reload)
    float p1A = 0.f, p2A = 0.f, p3A = 0.f;
    float p1B = 0.f, p2B = 0.f, p3B = 0.f;
    #pragma unroll
    for (int i = 0; i < 8; i++) {
        const float4 xa = x4[baseA + i * 32];
        const float4 xb = x4[baseB + i * 32];
        const int idx = i * 32 + lane;
        const float4 w1 = sW1[idx];
        p1A += xa.x * w1.x + xa.y * w1.y + xa.z * w1.z + xa.w * w1.w;
        p1B += xb.x * w1.x + xb.y * w1.y + xb.z * w1.z + xb.w * w1.w;
        const float4 w2 = sW2[idx];
        p2A += xa.x * w2.x + xa.y * w2.y + xa.z * w2.z + xa.w * w2.w;
        p2B += xb.x * w2.x + xb.y * w2.y + xb.z * w2.z + xb.w * w2.w;
        const float4 w3 = sW3[idx];
        p3A += xa.x * w3.x + xa.y * w3.y + xa.z * w3.z + xa.w * w3.w;
        p3B += xb.x * w3.x + xb.y * w3.y + xb.z * w3.z + xb.w * w3.w;
    }

    // interleaved butterflies: 6 independent chains
    #pragma unroll
    for (int o = 16; o > 0; o >>= 1) {
        p1A += __shfl_xor_sync(0xFFFFFFFFu, p1A, o);
        p1B += __shfl_xor_sync(0xFFFFFFFFu, p1B, o);
        p2A += __shfl_xor_sync(0xFFFFFFFFu, p2A, o);
        p2B += __shfl_xor_sync(0xFFFFFFFFu, p2B, o);
        p3A += __shfl_xor_sync(0xFFFFFFFFu, p3A, o);
        p3B += __shfl_xor_sync(0xFFFFFFFFu, p3B, o);
    }

    const float s1A = 1.0f + p1A;
    const float s2A = s1A + fmaf(s1A, p2A, c2);
    const float s3A = s2A + fmaf(s2A, p3A, c3);
    const float s1B = 1.0f + p1B;
    const float s2B = s1B + fmaf(s1B, p2B, c2);
    const float s3B = s2B + fmaf(s2B, p3B, c3);

    // output pass: re-load x (L1 hits), write streaming
    #pragma unroll
    for (int i = 0; i < 8; i++) {
        const float4 xa = x4[baseA + i * 32];
        const float4 xb = x4[baseB + i * 32];
        const float4 bs = sBs[i * 32 + lane];
        float4 oA, oB;
        oA.x = fmaf(xa.x, s3A, bs.x);
        oA.y = fmaf(xa.y, s3A, bs.y);
        oA.z = fmaf(xa.z, s3A, bs.z);
        oA.w = fmaf(xa.w, s3A, bs.w);
        __stcs(&out4[baseA + i * 32], oA);
        oB.x = fmaf(xb.x, s3B, bs.x);
        oB.y = fmaf(xb.y, s3B, bs.y);
        oB.z = fmaf(xb.z, s3B, bs.z);
        oB.w = fmaf(xb.w, s3B, bs.w);
        __stcs(&out4[baseB + i * 32], oB);
    }
}

extern "C" void kernel_launch(void* const* d_in, const int* in_sizes, int n_in,
                              void* d_out, int out_size)
{
    const float4* x4 = (const float4*)d_in[0];
    const float4* W4 = (const float4*)d_in[1];
    const float4* b4 = (const float4*)d_in[2];
    float4* out4 = (float4*)d_out;

    const int B = in_sizes[0] / D;   // 16384

    cross_layer_kernel<<<B / ROWS_PER_BLOCK, THREADS>>>(x4, W4, b4, out4);
}

// round 13
// speedup vs baseline: 1.3527x; 1.3527x over previous
#include <cuda_runtime.h>
#include <cstdint>

// CrossLayer DCN, closed form, cp.async-pipelined persistent kernel.
//   t_l = <x, W_l>;  s1 = 1+t1; s2 = s1 + (s1*t2 + c2); s3 = s2 + (s2*t3 + c3)
//   out = x * s3 + (b1+b2+b3);  c2 = <b1,W2>, c3 = <b1+b2,W3>
//
// grid = 148 persistent blocks (1/SM, smem-limited), 256 threads = 8 warps.
// Block strides over tiles of 16 rows (64KB). x staged via cp.async into a
// 3-deep smem ring; up to 2 tiles (128KB) in flight per SM -> MLP decoupled
// from registers. Each warp processes 2 rows from smem (W/bs LDS shared).

#define D 1024
#define DV 256                 // float4 per row
#define THREADS 256
#define WARPS 8
#define TILE_ROWS 16
#define TILE_F4 (TILE_ROWS * DV)   // 4096 float4 = 64KB
#define NBUF 3
#define GRID 148

#define SMEM_F4 (4 * DV + NBUF * TILE_F4)
#define SMEM_BYTES (SMEM_F4 * 16)   // 212992

__device__ __forceinline__ void cp16(uint32_t dst, const float4* src) {
    asm volatile("cp.async.cg.shared.global [%0], [%1], 16;" :: "r"(dst), "l"(src));
}
__device__ __forceinline__ void cp_commit() {
    asm volatile("cp.async.commit_group;" ::: "memory");
}
__device__ __forceinline__ void cp_wait2() {
    asm volatile("cp.async.wait_group 2;" ::: "memory");
}

__device__ __forceinline__ void issue_tile(const float4* __restrict__ x4,
                                           long tile, uint32_t sx_base,
                                           int buf, int tid)
{
    const float4* src = x4 + tile * TILE_F4;
    uint32_t dst = sx_base + (uint32_t)buf * (TILE_F4 * 16u);
    #pragma unroll
    for (int k = 0; k < TILE_F4 / THREADS; k++) {
        int idx = tid + k * THREADS;
        cp16(dst + (uint32_t)idx * 16u, src + idx);
    }
}

__global__ void __launch_bounds__(THREADS, 1)
cross_layer_kernel(const float4* __restrict__ x4,
                   const float4* __restrict__ W4,
                   const float4* __restrict__ b4,
                   float4* __restrict__ out4,
                   int ntiles)
{
    extern __shared__ float4 dsm[];
    float4* sW1 = dsm;
    float4* sW2 = dsm + DV;
    float4* sW3 = dsm + 2 * DV;
    float4* sBs = dsm + 3 * DV;
    float4* sX  = dsm + 4 * DV;
    __shared__ float2 sRed[WARPS];

    const int tid  = threadIdx.x;
    const int lane = tid & 31;
    const int wid  = tid >> 5;

    uint32_t sx_base;
    asm("{ .reg .u64 t; cvta.to.shared.u64 t, %1; cvt.u32.u64 %0, t; }"
        : "=r"(sx_base) : "l"(sX));

    const int stride = gridDim.x;
    const int t0 = blockIdx.x;
    int my_n = (t0 < ntiles) ? (ntiles - t0 + stride - 1) / stride : 0;

    // prologue prefetch (overlaps with W staging below)
    if (my_n > 0) issue_tile(x4, (long)t0, sx_base, 0, tid);
    cp_commit();
    if (my_n > 1) issue_tile(x4, (long)t0 + stride, sx_base, 1, tid);
    cp_commit();

    // ---- stage W/bsum -> smem; c2,c3 block-reduced ----
    {
        float4 w1 = __ldg(&W4[tid]);
        float4 w2 = __ldg(&W4[DV + tid]);
        float4 w3 = __ldg(&W4[2 * DV + tid]);
        float4 b1 = __ldg(&b4[tid]);
        float4 b2 = __ldg(&b4[DV + tid]);
        float4 b3 = __ldg(&b4[2 * DV + tid]);

        sW1[tid] = w1; sW2[tid] = w2; sW3[tid] = w3;
        float4 bs;
        bs.x = b1.x + b2.x + b3.x;
        bs.y = b1.y + b2.y + b3.y;
        bs.z = b1.z + b2.z + b3.z;
        bs.w = b1.w + b2.w + b3.w;
        sBs[tid] = bs;

        float p2 = b1.x * w2.x + b1.y * w2.y + b1.z * w2.z + b1.w * w2.w;
        float b12x = b1.x + b2.x, b12y = b1.y + b2.y;
        float b12z = b1.z + b2.z, b12w = b1.w + b2.w;
        float p3 = b12x * w3.x + b12y * w3.y + b12z * w3.z + b12w * w3.w;

        #pragma unroll
        for (int o = 16; o > 0; o >>= 1) {
            p2 += __shfl_xor_sync(0xFFFFFFFFu, p2, o);
            p3 += __shfl_xor_sync(0xFFFFFFFFu, p3, o);
        }
        if (lane == 0) sRed[wid] = make_float2(p2, p3);
    }
    __syncthreads();

    float c2 = 0.f, c3 = 0.f;
    #pragma unroll
    for (int i = 0; i < WARPS; i++) { c2 += sRed[i].x; c3 += sRed[i].y; }

    // ---- pipelined tile loop ----
    for (int i = 0; i < my_n; i++) {
        // barrier: everyone finished reading buf[(i+2)%3] (== buf[(i-1)%3])
        __syncthreads();
        if (i + 2 < my_n)
            issue_tile(x4, (long)t0 + (long)(i + 2) * stride, sx_base,
                       (i + 2) % NBUF, tid);
        cp_commit();
        cp_wait2();          // tile i's group complete (2 newer may pend)
        __syncthreads();     // make all threads' copies visible block-wide

        const long tile = (long)t0 + (long)i * stride;
        const float4* xa4 = sX + (i % NBUF) * TILE_F4 + (wid * 2) * DV;
        const float4* xb4 = xa4 + DV;

        float p1A = 0.f, p2A = 0.f, p3A = 0.f;
        float p1B = 0.f, p2B = 0.f, p3B = 0.f;
        #pragma unroll
        for (int k = 0; k < 8; k++) {
            const int idx = k * 32 + lane;
            const float4 xa = xa4[idx];
            const float4 xb = xb4[idx];
            const float4 w1 = sW1[idx];
            p1A += xa.x * w1.x + xa.y * w1.y + xa.z * w1.z + xa.w * w1.w;
            p1B += xb.x * w1.x + xb.y * w1.y + xb.z * w1.z + xb.w * w1.w;
            const float4 w2 = sW2[idx];
            p2A += xa.x * w2.x + xa.y * w2.y + xa.z * w2.z + xa.w * w2.w;
            p2B += xb.x * w2.x + xb.y * w2.y + xb.z * w2.z + xb.w * w2.w;
            const float4 w3 = sW3[idx];
            p3A += xa.x * w3.x + xa.y * w3.y + xa.z * w3.z + xa.w * w3.w;
            p3B += xb.x * w3.x + xb.y * w3.y + xb.z * w3.z + xb.w * w3.w;
        }

        #pragma unroll
        for (int o = 16; o > 0; o >>= 1) {
            p1A += __shfl_xor_sync(0xFFFFFFFFu, p1A, o);
            p1B += __shfl_xor_sync(0xFFFFFFFFu, p1B, o);
            p2A += __shfl_xor_sync(0xFFFFFFFFu, p2A, o);
            p2B += __shfl_xor_sync(0xFFFFFFFFu, p2B, o);
            p3A += __shfl_xor_sync(0xFFFFFFFFu, p3A, o);
            p3B += __shfl_xor_sync(0xFFFFFFFFu, p3B, o);
        }

        const float s1A = 1.0f + p1A;
        const float s2A = s1A + fmaf(s1A, p2A, c2);
        const float s3A = s2A + fmaf(s2A, p3A, c3);
        const float s1B = 1.0f + p1B;
        const float s2B = s1B + fmaf(s1B, p2B, c2);
        const float s3B = s2B + fmaf(s2B, p3B, c3);

        float4* oA4 = out4 + tile * TILE_F4 + (wid * 2) * DV;
        float4* oB4 = oA4 + DV;

        #pragma unroll
        for (int k = 0; k < 8; k++) {
            const int idx = k * 32 + lane;
            const float4 xa = xa4[idx];
            const float4 xb = xb4[idx];
            const float4 bs = sBs[idx];
            float4 oA, oB;
            oA.x = fmaf(xa.x, s3A, bs.x);
            oA.y = fmaf(xa.y, s3A, bs.y);
            oA.z = fmaf(xa.z, s3A, bs.z);
            oA.w = fmaf(xa.w, s3A, bs.w);
            __stcs(&oA4[idx], oA);
            oB.x = fmaf(xb.x, s3B, bs.x);
            oB.y = fmaf(xb.y, s3B, bs.y);
            oB.z = fmaf(xb.z, s3B, bs.z);
            oB.w = fmaf(xb.w, s3B, bs.w);
            __stcs(&oB4[idx], oB);
        }
    }
}

extern "C" void kernel_launch(void* const* d_in, const int* in_sizes, int n_in,
                              void* d_out, int out_size)
{
    const float4* x4 = (const float4*)d_in[0];
    const float4* W4 = (const float4*)d_in[1];
    const float4* b4 = (const float4*)d_in[2];
    float4* out4 = (float4*)d_out;

    const int B = in_sizes[0] / D;        // 16384
    const int ntiles = B / TILE_ROWS;     // 1024

    cudaFuncSetAttribute(cross_layer_kernel,
                         cudaFuncAttributeMaxDynamicSharedMemorySize,
                         SMEM_BYTES);

    cross_layer_kernel<<<GRID, THREADS, SMEM_BYTES>>>(x4, W4, b4, out4, ntiles);
}

// round 14
// speedup vs baseline: 1.4861x; 1.0986x over previous
#include <cuda_runtime.h>
#include <cstdint>

// CrossLayer DCN, closed form, WARP-PRIVATE cp.async pipelines.
//   t_l = <x, W_l>;  s1 = 1+t1; s2 = s1 + (s1*t2 + c2); s3 = s2 + (s2*t3 + c3)
//   out = x * s3 + (b1+b2+b3);  c2 = <b1,W2>, c3 = <b1+b2,W3>
//
// grid = 148 persistent blocks, 256 threads = 8 warps. Each warp runs its own
// cp.async pipeline over row-PAIRS (8KB each, 3-deep ring): issues its own
// copies, waits its own groups, reads only its own buffers. NO __syncthreads
// in the main loop -> 8 decoupled pipelines per SM, phases overlap freely.

#define D 1024
#define DV 256                    // float4 per row
#define THREADS 256
#define WARPS 8
#define PAIR_F4 (2 * DV)          // 512 float4 = 8KB per row-pair
#define NBUF 3
#define GRID 148
#define GWARPS (GRID * WARPS)     // 1184

#define SMEM_F4 (4 * DV + WARPS * NBUF * PAIR_F4)
#define SMEM_BYTES (SMEM_F4 * 16)   // 16KB + 192KB = 208KB

__device__ __forceinline__ void cp16(uint32_t dst, const float4* src) {
    asm volatile("cp.async.cg.shared.global [%0], [%1], 16;" :: "r"(dst), "l"(src));
}
__device__ __forceinline__ void cp_commit() {
    asm volatile("cp.async.commit_group;" ::: "memory");
}
__device__ __forceinline__ void cp_wait2() {
    asm volatile("cp.async.wait_group 2;" ::: "memory");
}

// warp-private: lane issues 16 cp.async for one row-pair (512 f4 / 32 lanes)
__device__ __forceinline__ void issue_pair(const float4* __restrict__ x4,
                                           long pair, uint32_t wbase,
                                           int buf, int lane)
{
    const float4* src = x4 + pair * PAIR_F4 + lane;
    uint32_t dst = wbase + (uint32_t)buf * (PAIR_F4 * 16u) + (uint32_t)lane * 16u;
    #pragma unroll
    for (int k = 0; k < PAIR_F4 / 32; k++)
        cp16(dst + k * 512u, src + k * 32);
}

__global__ void __launch_bounds__(THREADS, 1)
cross_layer_kernel(const float4* __restrict__ x4,
                   const float4* __restrict__ W4,
                   const float4* __restrict__ b4,
                   float4* __restrict__ out4,
                   int npairs)
{
    extern __shared__ float4 dsm[];
    float4* sW1 = dsm;
    float4* sW2 = dsm + DV;
    float4* sW3 = dsm + 2 * DV;
    float4* sBs = dsm + 3 * DV;
    float4* sX  = dsm + 4 * DV;
    __shared__ float2 sRed[WARPS];

    const int tid  = threadIdx.x;
    const int lane = tid & 31;
    const int wid  = tid >> 5;

    uint32_t wbase;   // this warp's buffer region
    {
        const float4* wp = sX + wid * (NBUF * PAIR_F4);
        asm("{ .reg .u64 t; cvta.to.shared.u64 t, %1; cvt.u32.u64 %0, t; }"
            : "=r"(wbase) : "l"(wp));
    }
    const float4* wreg = sX + wid * (NBUF * PAIR_F4);

    // global warp id strides over row-pairs
    const int g = blockIdx.x * WARPS + wid;
    const int my_n = (g < npairs) ? (npairs - g + GWARPS - 1) / GWARPS : 0;

    // warp-private prologue prefetch
    if (my_n > 0) issue_pair(x4, (long)g, wbase, 0, lane);
    cp_commit();
    if (my_n > 1) issue_pair(x4, (long)g + GWARPS, wbase, 1, lane);
    cp_commit();

    // ---- stage W/bsum -> smem; c2,c3 block-reduced (one-time barrier) ----
    {
        float4 w1 = __ldg(&W4[tid]);
        float4 w2 = __ldg(&W4[DV + tid]);
        float4 w3 = __ldg(&W4[2 * DV + tid]);
        float4 b1 = __ldg(&b4[tid]);
        float4 b2 = __ldg(&b4[DV + tid]);
        float4 b3 = __ldg(&b4[2 * DV + tid]);

        sW1[tid] = w1; sW2[tid] = w2; sW3[tid] = w3;
        float4 bs;
        bs.x = b1.x + b2.x + b3.x;
        bs.y = b1.y + b2.y + b3.y;
        bs.z = b1.z + b2.z + b3.z;
        bs.w = b1.w + b2.w + b3.w;
        sBs[tid] = bs;

        float p2 = b1.x * w2.x + b1.y * w2.y + b1.z * w2.z + b1.w * w2.w;
        float b12x = b1.x + b2.x, b12y = b1.y + b2.y;
        float b12z = b1.z + b2.z, b12w = b1.w + b2.w;
        float p3 = b12x * w3.x + b12y * w3.y + b12z * w3.z + b12w * w3.w;

        #pragma unroll
        for (int o = 16; o > 0; o >>= 1) {
            p2 += __shfl_xor_sync(0xFFFFFFFFu, p2, o);
            p3 += __shfl_xor_sync(0xFFFFFFFFu, p3, o);
        }
        if (lane == 0) sRed[wid] = make_float2(p2, p3);
    }
    __syncthreads();

    float c2 = 0.f, c3 = 0.f;
    #pragma unroll
    for (int i = 0; i < WARPS; i++) { c2 += sRed[i].x; c3 += sRed[i].y; }

    // ---- warp-private pipelined loop: NO block barriers ----
    for (int i = 0; i < my_n; i++) {
        if (i + 2 < my_n)
            issue_pair(x4, (long)g + (long)(i + 2) * GWARPS, wbase,
                       (i + 2) % NBUF, lane);
        cp_commit();
        cp_wait2();        // own group for pair i complete
        __syncwarp();      // cross-lane visibility of the warp's copies

        const long pair = (long)g + (long)i * GWARPS;
        const float4* xa4 = wreg + (i % NBUF) * PAIR_F4;
        const float4* xb4 = xa4 + DV;

        float p1A = 0.f, p2A = 0.f, p3A = 0.f;
        float p1B = 0.f, p2B = 0.f, p3B = 0.f;
        #pragma unroll
        for (int k = 0; k < 8; k++) {
            const int idx = k * 32 + lane;
            const float4 xa = xa4[idx];
            const float4 xb = xb4[idx];
            const float4 w1 = sW1[idx];
            p1A += xa.x * w1.x + xa.y * w1.y + xa.z * w1.z + xa.w * w1.w;
            p1B += xb.x * w1.x + xb.y * w1.y + xb.z * w1.z + xb.w * w1.w;
            const float4 w2 = sW2[idx];
            p2A += xa.x * w2.x + xa.y * w2.y + xa.z * w2.z + xa.w * w2.w;
            p2B += xb.x * w2.x + xb.y * w2.y + xb.z * w2.z + xb.w * w2.w;
            const float4 w3 = sW3[idx];
            p3A += xa.x * w3.x + xa.y * w3.y + xa.z * w3.z + xa.w * w3.w;
            p3B += xb.x * w3.x + xb.y * w3.y + xb.z * w3.z + xb.w * w3.w;
        }

        #pragma unroll
        for (int o = 16; o > 0; o >>= 1) {
            p1A += __shfl_xor_sync(0xFFFFFFFFu, p1A, o);
            p1B += __shfl_xor_sync(0xFFFFFFFFu, p1B, o);
            p2A += __shfl_xor_sync(0xFFFFFFFFu, p2A, o);
            p2B += __shfl_xor_sync(0xFFFFFFFFu, p2B, o);
            p3A += __shfl_xor_sync(0xFFFFFFFFu, p3A, o);
            p3B += __shfl_xor_sync(0xFFFFFFFFu, p3B, o);
        }

        const float s1A = 1.0f + p1A;
        const float s2A = s1A + fmaf(s1A, p2A, c2);
        const float s3A = s2A + fmaf(s2A, p3A, c3);
        const float s1B = 1.0f + p1B;
        const float s2B = s1B + fmaf(s1B, p2B, c2);
        const float s3B = s2B + fmaf(s2B, p3B, c3);

        float4* oA4 = out4 + pair * PAIR_F4;
        float4* oB4 = oA4 + DV;

        #pragma unroll
        for (int k = 0; k < 8; k++) {
            const int idx = k * 32 + lane;
            const float4 xa = xa4[idx];
            const float4 xb = xb4[idx];
            const float4 bs = sBs[idx];
            float4 oA, oB;
            oA.x = fmaf(xa.x, s3A, bs.x);
            oA.y = fmaf(xa.y, s3A, bs.y);
            oA.z = fmaf(xa.z, s3A, bs.z);
            oA.w = fmaf(xa.w, s3A, bs.w);
            __stcs(&oA4[idx], oA);
            oB.x = fmaf(xb.x, s3B, bs.x);
            oB.y = fmaf(xb.y, s3B, bs.y);
            oB.z = fmaf(xb.z, s3B, bs.z);
            oB.w = fmaf(xb.w, s3B, bs.w);
            __stcs(&oB4[idx], oB);
        }
    }
}

extern "C" void kernel_launch(void* const* d_in, const int* in_sizes, int n_in,
                              void* d_out, int out_size)
{
    const float4* x4 = (const float4*)d_in[0];
    const float4* W4 = (const float4*)d_in[1];
    const float4* b4 = (const float4*)d_in[2];
    float4* out4 = (float4*)d_out;

    const int B = in_sizes[0] / D;     // 16384
    const int npairs = B / 2;          // 8192

    cudaFuncSetAttribute(cross_layer_kernel,
                         cudaFuncAttributeMaxDynamicSharedMemorySize,
                         SMEM_BYTES);

    cross_layer_kernel<<<GRID, THREADS, SMEM_BYTES>>>(x4, W4, b4, out4, npairs);
}

// round 16
// speedup vs baseline: 1.6139x; 1.0860x over previous
#include <cuda_runtime.h>
#include <cstdint>

// CrossLayer DCN, closed form, warp-private cp.async pipelines, W + x in regs.
//   t_l = <x, W_l>;  s1 = 1+t1; s2 = s1 + (s1*t2 + c2); s3 = s2 + (s2*t3 + c3)
//   out = x * s3 + (b1+b2+b3);  c2 = <b1,W2>, c3 = <b1+b2,W3>
//
// grid = 148 persistent blocks, 256 threads = 8 warps, 1 block/SM (smem-bound)
// => registers are free (256/thread): W lives in 96 regs/thread, x row-pair
// held in 64 regs between dot and output pass. Smem LDS per pair drops
// 96 -> 40 LDS.128; crossbar halves; MIO issue chain shortens ~30%.
// Each warp runs its own cp.async ring (3 x 8KB), no block barriers in loop.

#define D 1024
#define DV 256                    // float4 per row
#define THREADS 256
#define WARPS 8
#define PAIR_F4 (2 * DV)          // 512 float4 = 8KB per row-pair
#define NBUF 3
#define GRID 148
#define GWARPS (GRID * WARPS)     // 1184

#define SMEM_F4 (DV + WARPS * NBUF * PAIR_F4)     // bs + rings
#define SMEM_BYTES (SMEM_F4 * 16)                 // 4KB + 192KB

__device__ __forceinline__ void cp16(uint32_t dst, const float4* src) {
    asm volatile("cp.async.cg.shared.global [%0], [%1], 16;" :: "r"(dst), "l"(src));
}
__device__ __forceinline__ void cp_commit() {
    asm volatile("cp.async.commit_group;" ::: "memory");
}
__device__ __forceinline__ void cp_wait2() {
    asm volatile("cp.async.wait_group 2;" ::: "memory");
}

__device__ __forceinline__ void issue_pair(const float4* __restrict__ x4,
                                           long pair, uint32_t wbase,
                                           int buf, int lane)
{
    const float4* src = x4 + pair * PAIR_F4 + lane;
    uint32_t dst = wbase + (uint32_t)buf * (PAIR_F4 * 16u) + (uint32_t)lane * 16u;
    #pragma unroll
    for (int k = 0; k < PAIR_F4 / 32; k++)
        cp16(dst + k * 512u, src + k * 32);
}

__global__ void __launch_bounds__(THREADS, 1)
cross_layer_kernel(const float4* __restrict__ x4,
                   const float4* __restrict__ W4,
                   const float4* __restrict__ b4,
                   float4* __restrict__ out4,
                   int npairs)
{
    extern __shared__ float4 dsm[];
    float4* sBs = dsm;
    float4* sX  = dsm + DV;
    __shared__ float2 sRed[WARPS];

    const int tid  = threadIdx.x;
    const int lane = tid & 31;
    const int wid  = tid >> 5;

    uint32_t wbase;
    {
        const float4* wp = sX + wid * (NBUF * PAIR_F4);
        asm("{ .reg .u64 t; cvta.to.shared.u64 t, %1; cvt.u32.u64 %0, t; }"
            : "=r"(wbase) : "l"(wp));
    }
    const float4* wreg = sX + wid * (NBUF * PAIR_F4);

    const int g = blockIdx.x * WARPS + wid;
    const int my_n = (g < npairs) ? (npairs - g + GWARPS - 1) / GWARPS : 0;

    // warp-private prologue prefetch (overlaps staging below)
    if (my_n > 0) issue_pair(x4, (long)g, wbase, 0, lane);
    cp_commit();
    if (my_n > 1) issue_pair(x4, (long)g + GWARPS, wbase, 1, lane);
    cp_commit();

    // ---- staging: bs -> smem; c2,c3 block-reduced (one-time barrier) ----
    {
        float4 b1 = __ldg(&b4[tid]);
        float4 b2 = __ldg(&b4[DV + tid]);
        float4 b3 = __ldg(&b4[2 * DV + tid]);
        float4 w2t = __ldg(&W4[DV + tid]);
        float4 w3t = __ldg(&W4[2 * DV + tid]);

        float4 bs;
        bs.x = b1.x + b2.x + b3.x;
        bs.y = b1.y + b2.y + b3.y;
        bs.z = b1.z + b2.z + b3.z;
        bs.w = b1.w + b2.w + b3.w;
        sBs[tid] = bs;

        float p2 = b1.x * w2t.x + b1.y * w2t.y + b1.z * w2t.z + b1.w * w2t.w;
        float b12x = b1.x + b2.x, b12y = b1.y + b2.y;
        float b12z = b1.z + b2.z, b12w = b1.w + b2.w;
        float p3 = b12x * w3t.x + b12y * w3t.y + b12z * w3t.z + b12w * w3t.w;

        #pragma unroll
        for (int o = 16; o > 0; o >>= 1) {
            p2 += __shfl_xor_sync(0xFFFFFFFFu, p2, o);
            p3 += __shfl_xor_sync(0xFFFFFFFFu, p3, o);
        }
        if (lane == 0) sRed[wid] = make_float2(p2, p3);
    }
    __syncthreads();

    float c2 = 0.f, c3 = 0.f;
    #pragma unroll
    for (int i = 0; i < WARPS; i++) { c2 += sRed[i].x; c3 += sRed[i].y; }

    // ---- W register-resident: per-thread slice {k*32+lane} (96 regs) ----
    float4 w1r[8], w2r[8], w3r[8];
    #pragma unroll
    for (int k = 0; k < 8; k++) {
        const int idx = k * 32 + lane;
        w1r[k] = __ldg(&W4[idx]);
        w2r[k] = __ldg(&W4[DV + idx]);
        w3r[k] = __ldg(&W4[2 * DV + idx]);
    }

    // ---- warp-private pipelined loop: NO block barriers ----
    for (int i = 0; i < my_n; i++) {
        if (i + 2 < my_n)
            issue_pair(x4, (long)g + (long)(i + 2) * GWARPS, wbase,
                       (i + 2) % NBUF, lane);
        cp_commit();
        cp_wait2();
        __syncwarp();

        const long pair = (long)g + (long)i * GWARPS;
        const float4* xa4 = wreg + (i % NBUF) * PAIR_F4;
        const float4* xb4 = xa4 + DV;

        // load x once into regs; dot with register W
        float4 xa[8], xb[8];
        float p1A = 0.f, p2A = 0.f, p3A = 0.f;
        float p1B = 0.f, p2B = 0.f, p3B = 0.f;
        #pragma unroll
        for (int k = 0; k < 8; k++) {
            const int idx = k * 32 + lane;
            xa[k] = xa4[idx];
            xb[k] = xb4[idx];
            p1A += xa[k].x * w1r[k].x + xa[k].y * w1r[k].y + xa[k].z * w1r[k].z + xa[k].w * w1r[k].w;
            p1B += xb[k].x * w1r[k].x + xb[k].y * w1r[k].y + xb[k].z * w1r[k].z + xb[k].w * w1r[k].w;
            p2A += xa[k].x * w2r[k].x + xa[k].y * w2r[k].y + xa[k].z * w2r[k].z + xa[k].w * w2r[k].w;
            p2B += xb[k].x * w2r[k].x + xb[k].y * w2r[k].y + xb[k].z * w2r[k].z + xb[k].w * w2r[k].w;
            p3A += xa[k].x * w3r[k].x + xa[k].y * w3r[k].y + xa[k].z * w3r[k].z + xa[k].w * w3r[k].w;
            p3B += xb[k].x * w3r[k].x + xb[k].y * w3r[k].y + xb[k].z * w3r[k].z + xb[k].w * w3r[k].w;
        }

        #pragma unroll
        for (int o = 16; o > 0; o >>= 1) {
            p1A += __shfl_xor_sync(0xFFFFFFFFu, p1A, o);
            p1B += __shfl_xor_sync(0xFFFFFFFFu, p1B, o);
            p2A += __shfl_xor_sync(0xFFFFFFFFu, p2A, o);
            p2B += __shfl_xor_sync(0xFFFFFFFFu, p2B, o);
            p3A += __shfl_xor_sync(0xFFFFFFFFu, p3A, o);
            p3B += __shfl_xor_sync(0xFFFFFFFFu, p3B, o);
        }

        const float s1A = 1.0f + p1A;
        const float s2A = s1A + fmaf(s1A, p2A, c2);
        const float s3A = s2A + fmaf(s2A, p3A, c3);
        const float s1B = 1.0f + p1B;
        const float s2B = s1B + fmaf(s1B, p2B, c2);
        const float s3B = s2B + fmaf(s2B, p3B, c3);

        float4* oA4 = out4 + pair * PAIR_F4;
        float4* oB4 = oA4 + DV;

        #pragma unroll
        for (int k = 0; k < 8; k++) {
            const int idx = k * 32 + lane;
            const float4 bs = sBs[idx];
            float4 oA, oB;
            oA.x = fmaf(xa[k].x, s3A, bs.x);
            oA.y = fmaf(xa[k].y, s3A, bs.y);
            oA.z = fmaf(xa[k].z, s3A, bs.z);
            oA.w = fmaf(xa[k].w, s3A, bs.w);
            __stcs(&oA4[idx], oA);
            oB.x = fmaf(xb[k].x, s3B, bs.x);
            oB.y = fmaf(xb[k].y, s3B, bs.y);
            oB.z = fmaf(xb[k].z, s3B, bs.z);
            oB.w = fmaf(xb[k].w, s3B, bs.w);
            __stcs(&oB4[idx], oB);
        }
    }
}

extern "C" void kernel_launch(void* const* d_in, const int* in_sizes, int n_in,
                              void* d_out, int out_size)
{
    const float4* x4 = (const float4*)d_in[0];
    const float4* W4 = (const float4*)d_in[1];
    const float4* b4 = (const float4*)d_in[2];
    float4* out4 = (float4*)d_out;

    const int B = in_sizes[0] / D;     // 16384
    const int npairs = B / 2;          // 8192

    cudaFuncSetAttribute(cross_layer_kernel,
                         cudaFuncAttributeMaxDynamicSharedMemorySize,
                         SMEM_BYTES);

    cross_layer_kernel<<<GRID, THREADS, SMEM_BYTES>>>(x4, W4, b4, out4, npairs);
}